// round 13
// baseline (speedup 1.0000x reference)
#include <cuda_runtime.h>
#include <cuda_bf16.h>
#include <cstdint>

#define BATCH 1024
#define HIDN  512
#define KP    1536          // packed K: [hi | lo | hi]
#define NB    8             // batch rows per scan CTA (128 CTAs)
#define CH    32            // scan chunk width
#define NCHW  (HIDN / CH)   // 16 scan chunks
#define NCHUNK 24           // KP / 64

typedef unsigned long long u64;
typedef unsigned int u32;

__device__ float g_h[BATCH * HIDN];
__device__ __align__(16) __nv_bfloat16 g_A3[BATCH * KP];
__device__ __align__(16) __nv_bfloat16 g_B3in[HIDN * KP];
__device__ __align__(16) __nv_bfloat16 g_B3out[HIDN * KP];
__device__ __align__(16) __nv_bfloat16 g_H3[BATCH * KP];
__device__ __align__(16) u32 g_WB[(HIDN - 1) * HIDN];   // bf16x2 {w, b}

// ---- helpers ------------------------------------------------------------
__device__ __forceinline__ float2 unpk_wb(u32 v) {
    __nv_bfloat162 t = *reinterpret_cast<__nv_bfloat162*>(&v);
    return __bfloat1622float2(t);
}
__device__ __forceinline__ u32 s2u(const void* p) {
    u32 a;
    asm("{ .reg .u64 t; cvta.to.shared.u64 t, %1; cvt.u32.u64 %0, t; }" : "=r"(a) : "l"(p));
    return a;
}
#define SWZ(x) ((x) ^ (((x) >> 3) & 0x70))

__device__ __forceinline__ void bsplit(float a, unsigned short& h, unsigned short& l) {
    __nv_bfloat16 hb = __float2bfloat16(a);
    __nv_bfloat16 lb = __float2bfloat16(a - __bfloat162float(hb));
    h = *(unsigned short*)&hb;
    l = *(unsigned short*)&lb;
}
__device__ __forceinline__ u32 packwb1(float w, float b) {
    __nv_bfloat16 wh = __float2bfloat16(w), bh = __float2bfloat16(b);
    return (u32)(*(unsigned short*)&wh) | ((u32)(*(unsigned short*)&bh) << 16);
}
__device__ __forceinline__ uint4 pack8(const unsigned short* s) {
    uint4 u;
    u.x = (u32)s[0] | ((u32)s[1] << 16);
    u.y = (u32)s[2] | ((u32)s[3] << 16);
    u.z = (u32)s[4] | ((u32)s[5] << 16);
    u.w = (u32)s[6] | ((u32)s[7] << 16);
    return u;
}

__device__ __forceinline__ void ldm4(u32 addr, u32& r0, u32& r1, u32& r2, u32& r3) {
    asm volatile("ldmatrix.sync.aligned.m8n8.x4.shared.b16 {%0,%1,%2,%3}, [%4];"
                 : "=r"(r0), "=r"(r1), "=r"(r2), "=r"(r3) : "r"(addr));
}
__device__ __forceinline__ void mma16816(float* c, const u32* a, const u32* b) {
    asm volatile("mma.sync.aligned.m16n8k16.row.col.f32.bf16.bf16.f32 "
                 "{%0,%1,%2,%3}, {%4,%5,%6,%7}, {%8,%9}, {%0,%1,%2,%3};"
                 : "+f"(c[0]), "+f"(c[1]), "+f"(c[2]), "+f"(c[3])
                 : "r"(a[0]), "r"(a[1]), "r"(a[2]), "r"(a[3]), "r"(b[0]), "r"(b[1]));
}
__device__ __forceinline__ void cpasync16(u32 dst, const void* src) {
    asm volatile("cp.async.cg.shared.global [%0], [%1], 16;" :: "r"(dst), "l"(src));
}

// ---------------------------------------------------------------------------
// prep: ALL conversions in one launch.
//   blocks [0,256):   convA   X -> A3 [hi|lo|hi]
//   blocks [256,320): convW   W_in  -> B3in  [Wh|Wh|Wl]
//   blocks [320,384): convW   W_out -> B3out
//   blocks [384,640): convWB  {Whh,Bhh} -> bf16x2
// ---------------------------------------------------------------------------
__device__ void convW_body(const float* __restrict__ W,
                           __nv_bfloat16* __restrict__ B3,
                           int idx2, int tid, float (*tile)[65])
{
    const int nb = (idx2 & 7) * 64, kb = (idx2 >> 3) * 64;
    #pragma unroll
    for (int it = 0; it < 16; it++) {
        int idx = tid + it * 256, r = idx >> 6, cn = idx & 63;
        tile[r][cn] = W[(size_t)(kb + r) * 512 + nb + cn];
    }
    __syncthreads();
    const int nl = tid >> 2, kq = (tid & 3) << 4;
    const int row = nb + nl;
    #pragma unroll
    for (int g = 0; g < 2; g++) {
        unsigned short hs[8], ls[8];
        #pragma unroll
        for (int e = 0; e < 8; e++)
            bsplit(tile[kq + g * 8 + e][nl], hs[e], ls[e]);
        uint4 hp = pack8(hs), lp = pack8(ls);
        __nv_bfloat16* base = B3 + (size_t)row * KP + kb + kq + g * 8;
        *(uint4*)(base)        = hp;
        *(uint4*)(base + 512)  = hp;
        *(uint4*)(base + 1024) = lp;
    }
}

__global__ __launch_bounds__(256) void prep(
    const float* __restrict__ X,
    const float* __restrict__ W_in, const float* __restrict__ W_out,
    const float* __restrict__ Whh,  const float* __restrict__ Bhh,
    __nv_bfloat16* __restrict__ A3,
    __nv_bfloat16* __restrict__ B3i, __nv_bfloat16* __restrict__ B3o,
    u32* __restrict__ WB)
{
    __shared__ float tile[64][65];
    const int b = blockIdx.x, tid = threadIdx.x;

    if (b < 256) {                       // convA
        int t = b * 256 + tid;
        int m = t >> 6, k8 = (t & 63) << 3;
        float4 v0 = *(const float4*)(X + (size_t)m * 512 + k8);
        float4 v1 = *(const float4*)(X + (size_t)m * 512 + k8 + 4);
        float a[8] = {v0.x, v0.y, v0.z, v0.w, v1.x, v1.y, v1.z, v1.w};
        unsigned short hs[8], ls[8];
        #pragma unroll
        for (int e = 0; e < 8; e++) bsplit(a[e], hs[e], ls[e]);
        uint4 hp = pack8(hs), lp = pack8(ls);
        __nv_bfloat16* base = A3 + (size_t)m * KP + k8;
        *(uint4*)(base)        = hp;
        *(uint4*)(base + 512)  = lp;
        *(uint4*)(base + 1024) = hp;
    } else if (b < 320) {                // convW (W_in)
        convW_body(W_in, B3i, b - 256, tid, tile);
    } else if (b < 384) {                // convW (W_out)
        convW_body(W_out, B3o, b - 320, tid, tile);
    } else {                             // convWB
        int i4 = ((b - 384) * 256 + tid) * 4;
        if (i4 < (HIDN - 1) * HIDN) {
            float4 w = *(const float4*)(Whh + i4);
            float4 bb = *(const float4*)(Bhh + i4);
            uint4 o;
            o.x = packwb1(w.x, bb.x);
            o.y = packwb1(w.y, bb.y);
            o.z = packwb1(w.z, bb.z);
            o.w = packwb1(w.w, bb.w);
            *(uint4*)(WB + i4) = o;
        }
    }
}

// ---------------------------------------------------------------------------
// Warp-MMA bf16 GEMM (R12): CTA 64x32, 256 threads = 4x2 warps of 16x16,
// grid 16x16, 3-stage cp.async + register double-buffered fragments.
// ---------------------------------------------------------------------------
__global__ __launch_bounds__(256) void mma_gemm(
    const __nv_bfloat16* __restrict__ A3, const __nv_bfloat16* __restrict__ B3,
    const float* __restrict__ bias, float* __restrict__ C, int act)
{
    __shared__ __align__(128) char As[3 * 8192];
    __shared__ __align__(128) char Bs[3 * 4096];

    const int tid = threadIdx.x, wid = tid >> 5, lane = tid & 31;
    const int wm = wid >> 1, wn = wid & 1;
    const int mbase = blockIdx.y * 64, nbase = blockIdx.x * 32;
    const u32 sA = s2u(As), sB = s2u(Bs);

    const int idx = lane >> 3, lrow = lane & 7;
    u32 off_a[4], off_b[4];
    #pragma unroll
    for (int ks = 0; ks < 4; ks++) {
        int m_off = wm * 16 + (idx & 1) * 8 + lrow;
        int kba   = ks * 32 + (idx >> 1) * 16;
        off_a[ks] = SWZ(m_off * 128 + kba);
        int n_off = wn * 16 + (idx >> 1) * 8 + lrow;
        int kbb   = ks * 32 + (idx & 1) * 16;
        off_b[ks] = SWZ(n_off * 128 + kbb);
    }

    float acc[2][4];
    #pragma unroll
    for (int nt = 0; nt < 2; nt++)
        #pragma unroll
        for (int e = 0; e < 4; e++) acc[nt][e] = 0.0f;

    const int sr = tid >> 3, sq = tid & 7;

    #pragma unroll
    for (int pc = 0; pc < 2; pc++) {
        #pragma unroll
        for (int i = 0; i < 2; i++) {
            int r = sr + i * 32;
            cpasync16(sA + pc * 8192 + SWZ(r * 128 + sq * 16),
                      A3 + (size_t)(mbase + r) * KP + pc * 64 + sq * 8);
        }
        cpasync16(sB + pc * 4096 + SWZ(sr * 128 + sq * 16),
                  B3 + (size_t)(nbase + sr) * KP + pc * 64 + sq * 8);
        asm volatile("cp.async.commit_group;");
    }

    for (int c = 0; c < NCHUNK; c++) {
        if (c + 1 < NCHUNK) asm volatile("cp.async.wait_group 1;");
        else                asm volatile("cp.async.wait_group 0;");
        __syncthreads();

        const int slot = c % 3;
        const u32 ab = sA + slot * 8192, bb = sB + slot * 4096;

        u32 af[2][4], bf[2][4];
        ldm4(ab + off_a[0], af[0][0], af[0][1], af[0][2], af[0][3]);
        ldm4(bb + off_b[0], bf[0][0], bf[0][1], bf[0][2], bf[0][3]);

        #pragma unroll
        for (int ks = 0; ks < 4; ks++) {
            const int cur = ks & 1, nx = cur ^ 1;
            if (ks < 3) {
                ldm4(ab + off_a[ks + 1], af[nx][0], af[nx][1], af[nx][2], af[nx][3]);
                ldm4(bb + off_b[ks + 1], bf[nx][0], bf[nx][1], bf[nx][2], bf[nx][3]);
            }
            mma16816(acc[0], af[cur], &bf[cur][0]);
            mma16816(acc[1], af[cur], &bf[cur][2]);
        }

        if (c + 2 < NCHUNK) {
            const int ns = (c + 2) % 3;
            #pragma unroll
            for (int i = 0; i < 2; i++) {
                int r = sr + i * 32;
                cpasync16(sA + ns * 8192 + SWZ(r * 128 + sq * 16),
                          A3 + (size_t)(mbase + r) * KP + (c + 2) * 64 + sq * 8);
            }
            cpasync16(sB + ns * 4096 + SWZ(sr * 128 + sq * 16),
                      B3 + (size_t)(nbase + sr) * KP + (c + 2) * 64 + sq * 8);
            asm volatile("cp.async.commit_group;");
        }
    }

    const int row = mbase + wm * 16 + (lane >> 2);
    #pragma unroll
    for (int nt = 0; nt < 2; nt++) {
        const int col = nbase + wn * 16 + nt * 8 + (lane & 3) * 2;
        float2 bv = *(const float2*)&bias[col];
        float2 o1 = make_float2(acc[nt][0] + bv.x, acc[nt][1] + bv.y);
        float2 o2 = make_float2(acc[nt][2] + bv.x, acc[nt][3] + bv.y);
        if (act) {
            float r;
            r = fmaxf(o1.x, 0.0f); o1.x = r * r;
            r = fmaxf(o1.y, 0.0f); o1.y = r * r;
            r = fmaxf(o2.x, 0.0f); o2.x = r * r;
            r = fmaxf(o2.y, 0.0f); o2.y = r * r;
        }
        *(float2*)&C[(size_t)row * HIDN + col]       = o1;
        *(float2*)&C[(size_t)(row + 8) * HIDN + col] = o2;
    }
}

// ---------------------------------------------------------------------------
// Flag-pipelined sequential scan, NB=8, bf16x2 WB loads, SCALAR fp32 apply
// math (3 instr/element: FFMA + FMNMX + FFMA, split across fma/alu pipes).
// ---------------------------------------------------------------------------
__global__ __launch_bounds__(512) void scan_kernel(
    const float* __restrict__ Whh, const float* __restrict__ Bhh,
    const u32* __restrict__ WB)
{
    const int j    = threadIdx.x;
    const int w    = j >> 5;
    const int l    = j & 31;
    const int row0 = blockIdx.x * NB;

    __shared__ __align__(16) float bc[NCHW][CH][NB];
    __shared__ int flag[NCHW];

    if (j < NCHW) flag[j] = 0;
    __syncthreads();
    volatile int* vflag = flag;

    float h[NB];
    #pragma unroll
    for (int p = 0; p < NB; p++)
        h[p] = g_h[(size_t)(row0 + p) * HIDN + j];

    // ---- apply earlier chunks as they are published ----
    for (int c = 0; c < w; c++) {
        const int base = c << 5;
        u32 wb0[16];
        #pragma unroll
        for (int q = 0; q < 16; q++)
            wb0[q] = WB[(size_t)(base + q) * HIDN + j];
        while (vflag[c] == 0) { __nanosleep(64); }
        __threadfence_block();

        u32 wb1[16];
        #pragma unroll
        for (int q = 0; q < 16; q++)
            wb1[q] = WB[(size_t)(base + 16 + q) * HIDN + j];

        #pragma unroll
        for (int q = 0; q < 16; q++) {
            float4 s0 = *(const float4*)&bc[c][q][0];
            float4 s1 = *(const float4*)&bc[c][q][4];
            float s[NB] = {s0.x, s0.y, s0.z, s0.w, s1.x, s1.y, s1.z, s1.w};
            float2 f = unpk_wb(wb0[q]);
            #pragma unroll
            for (int p = 0; p < NB; p++) {
                float v = fmaf(s[p], f.x, f.y);
                float r = fmaxf(v, 0.0f);
                h[p] = fmaf(r, r, h[p]);
            }
        }
        #pragma unroll
        for (int q = 0; q < 16; q++) {
            float4 s0 = *(const float4*)&bc[c][16 + q][0];
            float4 s1 = *(const float4*)&bc[c][16 + q][4];
            float s[NB] = {s0.x, s0.y, s0.z, s0.w, s1.x, s1.y, s1.z, s1.w};
            float2 f = unpk_wb(wb1[q]);
            #pragma unroll
            for (int p = 0; p < NB; p++) {
                float v = fmaf(s[p], f.x, f.y);
                float r = fmaxf(v, 0.0f);
                h[p] = fmaf(r, r, h[p]);
            }
        }
    }

    // ---- intra-warp sequential scan of own chunk (fp32 W/B) ----
    const int cbase = w << 5;
    #pragma unroll
    for (int half = 0; half < 2; half++) {
        float wr[16], br[16];
        #pragma unroll
        for (int q = 0; q < 16; q++) {
            int i = cbase + half * 16 + q;
            bool valid = (i < HIDN - 1);
            wr[q] = valid ? Whh[(size_t)i * HIDN + j] : 0.0f;
            br[q] = valid ? Bhh[(size_t)i * HIDN + j] : 0.0f;
        }
        #pragma unroll
        for (int q = 0; q < 16; q++) {
            const int il = half * 16 + q;
            float s[NB];
            #pragma unroll
            for (int p = 0; p < NB; p++)
                s[p] = __shfl_sync(0xffffffffu, h[p], il);
            if (l > il) {
                #pragma unroll
                for (int p = 0; p < NB; p++) {
                    float v = fmaf(s[p], wr[q], br[q]);
                    float r = fmaxf(v, 0.0f);
                    h[p] = fmaf(r, r, h[p]);
                }
            }
        }
    }

    // ---- publish + final store ----
    if (w < NCHW - 1) {
        *(float4*)&bc[w][l][0] = make_float4(h[0], h[1], h[2], h[3]);
        *(float4*)&bc[w][l][4] = make_float4(h[4], h[5], h[6], h[7]);
        __threadfence_block();
        if (l == 0) vflag[w] = 1;
    }

    // write bf16-split h directly for GEMM2
    #pragma unroll
    for (int p = 0; p < NB; p++) {
        int r0 = row0 + p;
        unsigned short hh, ll;
        bsplit(h[p], hh, ll);
        *(unsigned short*)&g_H3[(size_t)r0 * KP + j]        = hh;
        *(unsigned short*)&g_H3[(size_t)r0 * KP + 512 + j]  = ll;
        *(unsigned short*)&g_H3[(size_t)r0 * KP + 1024 + j] = hh;
    }
}

// ---------------------------------------------------------------------------
extern "C" void kernel_launch(void* const* d_in, const int* in_sizes, int n_in,
                              void* d_out, int out_size)
{
    const float* x     = (const float*)d_in[0];
    const float* W_in  = (const float*)d_in[1];
    const float* b_in  = (const float*)d_in[2];
    const float* W_hh  = (const float*)d_in[3];
    const float* b_hh  = (const float*)d_in[4];
    const float* W_out = (const float*)d_in[5];
    const float* b_out = (const float*)d_in[6];
    float* out = (float*)d_out;

    float* hptr = nullptr;
    __nv_bfloat16 *a3 = nullptr, *b3i = nullptr, *b3o = nullptr, *h3 = nullptr;
    u32* wb = nullptr;
    cudaGetSymbolAddress((void**)&hptr, g_h);
    cudaGetSymbolAddress((void**)&a3,  g_A3);
    cudaGetSymbolAddress((void**)&b3i, g_B3in);
    cudaGetSymbolAddress((void**)&b3o, g_B3out);
    cudaGetSymbolAddress((void**)&h3,  g_H3);
    cudaGetSymbolAddress((void**)&wb,  g_WB);

    prep<<<640, 256>>>(x, W_in, W_out, W_hh, b_hh, a3, b3i, b3o, wb);

    mma_gemm<<<dim3(HIDN / 32, BATCH / 64), 256>>>(a3, b3i, b_in, hptr, 1);

    scan_kernel<<<BATCH / NB, 512>>>(W_hh, b_hh, wb);

    mma_gemm<<<dim3(HIDN / 32, BATCH / 64), 256>>>(h3, b3o, b_out, out, 0);
}

// round 14
// speedup vs baseline: 1.2075x; 1.2075x over previous
#include <cuda_runtime.h>
#include <cuda_bf16.h>
#include <cstdint>

#define BATCH 1024
#define HIDN  512
#define KP    1536          // packed K: [hi | lo | hi]
#define NB    8             // batch rows per scan CTA (128 CTAs)
#define CH    32            // scan chunk width
#define NCHW  (HIDN / CH)   // 16 scan chunks
#define NCH2  12            // KP / 128  (GEMM K-chunks of 128)

typedef unsigned long long u64;
typedef unsigned int u32;

__device__ float g_h[BATCH * HIDN];
__device__ __align__(16) __nv_bfloat16 g_A3[BATCH * KP];
__device__ __align__(16) __nv_bfloat16 g_B3in[HIDN * KP];
__device__ __align__(16) __nv_bfloat16 g_B3out[HIDN * KP];
__device__ __align__(16) __nv_bfloat16 g_H3[BATCH * KP];

// ---- f32x2 helpers ----------------------------------------------------------
__device__ __forceinline__ u64 pack2(float v) {
    u64 r; asm("mov.b64 %0, {%1, %1};" : "=l"(r) : "f"(v)); return r;
}
__device__ __forceinline__ u64 packxy(float x, float y) {
    u64 r; asm("mov.b64 %0, {%1, %2};" : "=l"(r) : "f"(x), "f"(y)); return r;
}
__device__ __forceinline__ float2 unpk(u64 v) {
    float2 f; asm("mov.b64 {%0, %1}, %2;" : "=f"(f.x), "=f"(f.y) : "l"(v)); return f;
}
__device__ __forceinline__ u64 fma2v(u64 a, u64 b, u64 c) {
    u64 d; asm("fma.rn.f32x2 %0, %1, %2, %3;" : "=l"(d) : "l"(a), "l"(b), "l"(c)); return d;
}
__device__ __forceinline__ u64 max2z(u64 v) {
    u64 m;
    asm("{\n\t.reg .f32 a, b;\n\t"
        "mov.b64 {a, b}, %1;\n\t"
        "max.f32 a, a, 0f00000000;\n\t"
        "max.f32 b, b, 0f00000000;\n\t"
        "mov.b64 %0, {a, b};\n\t}"
        : "=l"(m) : "l"(v));
    return m;
}

// ---- misc helpers -----------------------------------------------------------
__device__ __forceinline__ u32 s2u(const void* p) {
    u32 a;
    asm("{ .reg .u64 t; cvta.to.shared.u64 t, %1; cvt.u32.u64 %0, t; }" : "=r"(a) : "l"(p));
    return a;
}
#define SWZ(x) ((x) ^ (((x) >> 3) & 0x70))

__device__ __forceinline__ void bsplit(float a, unsigned short& h, unsigned short& l) {
    __nv_bfloat16 hb = __float2bfloat16(a);
    __nv_bfloat16 lb = __float2bfloat16(a - __bfloat162float(hb));
    h = *(unsigned short*)&hb;
    l = *(unsigned short*)&lb;
}
__device__ __forceinline__ uint4 pack8(const unsigned short* s) {
    uint4 u;
    u.x = (u32)s[0] | ((u32)s[1] << 16);
    u.y = (u32)s[2] | ((u32)s[3] << 16);
    u.z = (u32)s[4] | ((u32)s[5] << 16);
    u.w = (u32)s[6] | ((u32)s[7] << 16);
    return u;
}

__device__ __forceinline__ void ldm4(u32 addr, u32& r0, u32& r1, u32& r2, u32& r3) {
    asm volatile("ldmatrix.sync.aligned.m8n8.x4.shared.b16 {%0,%1,%2,%3}, [%4];"
                 : "=r"(r0), "=r"(r1), "=r"(r2), "=r"(r3) : "r"(addr));
}
__device__ __forceinline__ void mma16816(float* c, const u32* a, const u32* b) {
    asm volatile("mma.sync.aligned.m16n8k16.row.col.f32.bf16.bf16.f32 "
                 "{%0,%1,%2,%3}, {%4,%5,%6,%7}, {%8,%9}, {%0,%1,%2,%3};"
                 : "+f"(c[0]), "+f"(c[1]), "+f"(c[2]), "+f"(c[3])
                 : "r"(a[0]), "r"(a[1]), "r"(a[2]), "r"(a[3]), "r"(b[0]), "r"(b[1]));
}
__device__ __forceinline__ void cpasync16(u32 dst, const void* src) {
    asm volatile("cp.async.cg.shared.global [%0], [%1], 16;" :: "r"(dst), "l"(src));
}

// ---------------------------------------------------------------------------
// convA: X [M,512] fp32 -> A3 [M,1536] bf16 = [hi | lo | hi]
// ---------------------------------------------------------------------------
__global__ __launch_bounds__(256) void convA(
    const float* __restrict__ X, __nv_bfloat16* __restrict__ A3)
{
    int t = blockIdx.x * 256 + threadIdx.x;
    int m = t >> 6, k8 = (t & 63) << 3;
    float4 v0 = *(const float4*)(X + (size_t)m * 512 + k8);
    float4 v1 = *(const float4*)(X + (size_t)m * 512 + k8 + 4);
    float a[8] = {v0.x, v0.y, v0.z, v0.w, v1.x, v1.y, v1.z, v1.w};
    unsigned short hs[8], ls[8];
    #pragma unroll
    for (int e = 0; e < 8; e++) bsplit(a[e], hs[e], ls[e]);
    uint4 hp = pack8(hs), lp = pack8(ls);
    __nv_bfloat16* base = A3 + (size_t)m * KP + k8;
    *(uint4*)(base)        = hp;
    *(uint4*)(base + 512)  = lp;
    *(uint4*)(base + 1024) = hp;
}

// ---------------------------------------------------------------------------
// convW: W [512(k),512(n)] fp32 -> B3 [n][1536] bf16 = [Wh | Wh | Wl] (K-major)
// ---------------------------------------------------------------------------
__global__ __launch_bounds__(256) void convW(
    const float* __restrict__ W, __nv_bfloat16* __restrict__ B3)
{
    __shared__ float tile[64][65];
    const int kb = blockIdx.y * 64, nb = blockIdx.x * 64, tid = threadIdx.x;
    #pragma unroll
    for (int it = 0; it < 16; it++) {
        int idx = tid + it * 256, r = idx >> 6, cn = idx & 63;
        tile[r][cn] = W[(size_t)(kb + r) * 512 + nb + cn];
    }
    __syncthreads();
    const int nl = tid >> 2, kq = (tid & 3) << 4;
    const int row = nb + nl;
    #pragma unroll
    for (int g = 0; g < 2; g++) {
        unsigned short hs[8], ls[8];
        #pragma unroll
        for (int e = 0; e < 8; e++)
            bsplit(tile[kq + g * 8 + e][nl], hs[e], ls[e]);
        uint4 hp = pack8(hs), lp = pack8(ls);
        __nv_bfloat16* base = B3 + (size_t)row * KP + kb + kq + g * 8;
        *(uint4*)(base)        = hp;
        *(uint4*)(base + 512)  = hp;
        *(uint4*)(base + 1024) = lp;
    }
}

// ---------------------------------------------------------------------------
// Warp-MMA bf16 GEMM: C = act?(A3 . B3^T + bias)
// CTA 64x32, 128 threads = 2x2 warps of 32x16 tiles (R10 fragment layout),
// K-chunks of 128 stored as TWO 64-wide sub-tiles -> 12 barriers, 3 stages.
// ---------------------------------------------------------------------------
__global__ __launch_bounds__(128) void mma_gemm(
    const __nv_bfloat16* __restrict__ A3, const __nv_bfloat16* __restrict__ B3,
    const float* __restrict__ bias, float* __restrict__ C, int act)
{
    __shared__ __align__(128) char As[3 * 16384];   // per stage: 2 sub-tiles x 8KB
    __shared__ __align__(128) char Bs[3 * 8192];    // per stage: 2 sub-tiles x 4KB

    const int tid = threadIdx.x, wid = tid >> 5, lane = tid & 31;
    const int wm = wid >> 1, wn = wid & 1;
    const int mbase = blockIdx.y * 64, nbase = blockIdx.x * 32;
    const u32 sA = s2u(As), sB = s2u(Bs);

    const int idx = lane >> 3, lrow = lane & 7;
    u32 off_a[2][4], off_b[4];
    #pragma unroll
    for (int mt = 0; mt < 2; mt++)
        #pragma unroll
        for (int ks = 0; ks < 4; ks++) {
            int m_off = wm * 32 + mt * 16 + (idx & 1) * 8 + lrow;
            int kb    = ks * 32 + (idx >> 1) * 16;
            off_a[mt][ks] = SWZ(m_off * 128 + kb);
        }
    #pragma unroll
    for (int ks = 0; ks < 4; ks++) {
        int n_off = wn * 16 + (idx >> 1) * 8 + lrow;
        int kb    = ks * 32 + (idx & 1) * 16;
        off_b[ks] = SWZ(n_off * 128 + kb);
    }

    float acc[2][2][4];
    #pragma unroll
    for (int mt = 0; mt < 2; mt++)
        #pragma unroll
        for (int nt = 0; nt < 2; nt++)
            #pragma unroll
            for (int e = 0; e < 4; e++) acc[mt][nt][e] = 0.0f;

    // staging (128 threads): per sub-tile A 4 loads/thread, B 2 loads/thread
    const int sr = tid >> 3, sq = tid & 7;   // sr 0..15

    #pragma unroll
    for (int pc = 0; pc < 2; pc++) {
        #pragma unroll
        for (int s = 0; s < 2; s++) {
            #pragma unroll
            for (int i = 0; i < 4; i++) {
                int r = sr + i * 16;
                cpasync16(sA + pc * 16384 + s * 8192 + SWZ(r * 128 + sq * 16),
                          A3 + (size_t)(mbase + r) * KP + pc * 128 + s * 64 + sq * 8);
            }
            #pragma unroll
            for (int i = 0; i < 2; i++) {
                int r = sr + i * 16;
                cpasync16(sB + pc * 8192 + s * 4096 + SWZ(r * 128 + sq * 16),
                          B3 + (size_t)(nbase + r) * KP + pc * 128 + s * 64 + sq * 8);
            }
        }
        asm volatile("cp.async.commit_group;");
    }

    for (int c = 0; c < NCH2; c++) {
        if (c + 1 < NCH2) asm volatile("cp.async.wait_group 1;");
        else              asm volatile("cp.async.wait_group 0;");
        __syncthreads();

        const int slot = c % 3;
        #pragma unroll
        for (int s = 0; s < 2; s++) {
            const u32 ab = sA + slot * 16384 + s * 8192;
            const u32 bb = sB + slot * 8192  + s * 4096;
            #pragma unroll
            for (int ks = 0; ks < 4; ks++) {
                u32 af[2][4], bf[4];
                ldm4(ab + off_a[0][ks], af[0][0], af[0][1], af[0][2], af[0][3]);
                ldm4(ab + off_a[1][ks], af[1][0], af[1][1], af[1][2], af[1][3]);
                ldm4(bb + off_b[ks], bf[0], bf[1], bf[2], bf[3]);
                mma16816(acc[0][0], af[0], &bf[0]);
                mma16816(acc[0][1], af[0], &bf[2]);
                mma16816(acc[1][0], af[1], &bf[0]);
                mma16816(acc[1][1], af[1], &bf[2]);
            }
        }

        if (c + 2 < NCH2) {
            const int ns = (c + 2) % 3;
            #pragma unroll
            for (int s = 0; s < 2; s++) {
                #pragma unroll
                for (int i = 0; i < 4; i++) {
                    int r = sr + i * 16;
                    cpasync16(sA + ns * 16384 + s * 8192 + SWZ(r * 128 + sq * 16),
                              A3 + (size_t)(mbase + r) * KP + (c + 2) * 128 + s * 64 + sq * 8);
                }
                #pragma unroll
                for (int i = 0; i < 2; i++) {
                    int r = sr + i * 16;
                    cpasync16(sB + ns * 8192 + s * 4096 + SWZ(r * 128 + sq * 16),
                              B3 + (size_t)(nbase + r) * KP + (c + 2) * 128 + s * 64 + sq * 8);
                }
            }
            asm volatile("cp.async.commit_group;");
        }
    }

    #pragma unroll
    for (int mt = 0; mt < 2; mt++) {
        const int row = mbase + wm * 32 + mt * 16 + (lane >> 2);
        #pragma unroll
        for (int nt = 0; nt < 2; nt++) {
            const int col = nbase + wn * 16 + nt * 8 + (lane & 3) * 2;
            float2 bv = *(const float2*)&bias[col];
            float2 o1 = make_float2(acc[mt][nt][0] + bv.x, acc[mt][nt][1] + bv.y);
            float2 o2 = make_float2(acc[mt][nt][2] + bv.x, acc[mt][nt][3] + bv.y);
            if (act) {
                float r;
                r = fmaxf(o1.x, 0.0f); o1.x = r * r;
                r = fmaxf(o1.y, 0.0f); o1.y = r * r;
                r = fmaxf(o2.x, 0.0f); o2.x = r * r;
                r = fmaxf(o2.y, 0.0f); o2.y = r * r;
            }
            *(float2*)&C[(size_t)row * HIDN + col]       = o1;
            *(float2*)&C[(size_t)(row + 8) * HIDN + col] = o2;
        }
    }
}

// ---------------------------------------------------------------------------
// Flag-pipelined sequential scan, NB=8 — EXACT R10 kernel.
// ---------------------------------------------------------------------------
__global__ __launch_bounds__(512) void scan_kernel(
    const float* __restrict__ Whh, const float* __restrict__ Bhh)
{
    const int j    = threadIdx.x;
    const int w    = j >> 5;
    const int l    = j & 31;
    const int row0 = blockIdx.x * NB;

    __shared__ __align__(16) float bc[NCHW][CH][NB];
    __shared__ int flag[NCHW];

    if (j < NCHW) flag[j] = 0;
    __syncthreads();
    volatile int* vflag = flag;

    u64 h2[4];
    #pragma unroll
    for (int p = 0; p < 4; p++)
        h2[p] = packxy(g_h[(size_t)(row0 + 2 * p) * HIDN + j],
                       g_h[(size_t)(row0 + 2 * p + 1) * HIDN + j]);

    for (int c = 0; c < w; c++) {
        const int base = c << 5;
        float wv0[16], bv0[16];
        #pragma unroll
        for (int q = 0; q < 16; q++) {
            wv0[q] = Whh[(size_t)(base + q) * HIDN + j];
            bv0[q] = Bhh[(size_t)(base + q) * HIDN + j];
        }
        while (vflag[c] == 0) { __nanosleep(64); }
        __threadfence_block();

        float wv1[16], bv1[16];
        #pragma unroll
        for (int q = 0; q < 16; q++) {
            wv1[q] = Whh[(size_t)(base + 16 + q) * HIDN + j];
            bv1[q] = Bhh[(size_t)(base + 16 + q) * HIDN + j];
        }

        #pragma unroll
        for (int q = 0; q < 16; q++) {
            ulonglong2 s01 = *(const ulonglong2*)&bc[c][q][0];
            ulonglong2 s23 = *(const ulonglong2*)&bc[c][q][4];
            u64 s2[4] = {s01.x, s01.y, s23.x, s23.y};
            u64 wd = pack2(wv0[q]), bd = pack2(bv0[q]);
            #pragma unroll
            for (int p = 0; p < 4; p++) {
                u64 m = max2z(fma2v(s2[p], wd, bd));
                h2[p] = fma2v(m, m, h2[p]);
            }
        }
        #pragma unroll
        for (int q = 0; q < 16; q++) {
            ulonglong2 s01 = *(const ulonglong2*)&bc[c][16 + q][0];
            ulonglong2 s23 = *(const ulonglong2*)&bc[c][16 + q][4];
            u64 s2[4] = {s01.x, s01.y, s23.x, s23.y};
            u64 wd = pack2(wv1[q]), bd = pack2(bv1[q]);
            #pragma unroll
            for (int p = 0; p < 4; p++) {
                u64 m = max2z(fma2v(s2[p], wd, bd));
                h2[p] = fma2v(m, m, h2[p]);
            }
        }
    }

    const int cbase = w << 5;
    #pragma unroll
    for (int half = 0; half < 2; half++) {
        float wr[16], br[16];
        #pragma unroll
        for (int q = 0; q < 16; q++) {
            int i = cbase + half * 16 + q;
            bool valid = (i < HIDN - 1);
            wr[q] = valid ? Whh[(size_t)i * HIDN + j] : 0.0f;
            br[q] = valid ? Bhh[(size_t)i * HIDN + j] : 0.0f;
        }
        #pragma unroll
        for (int q = 0; q < 16; q++) {
            const int il = half * 16 + q;
            u64 s2[4];
            #pragma unroll
            for (int p = 0; p < 4; p++)
                s2[p] = __shfl_sync(0xffffffffu, h2[p], il);
            if (l > il) {
                u64 wd = pack2(wr[q]), bd = pack2(br[q]);
                #pragma unroll
                for (int p = 0; p < 4; p++) {
                    u64 m = max2z(fma2v(s2[p], wd, bd));
                    h2[p] = fma2v(m, m, h2[p]);
                }
            }
        }
    }

    if (w < NCHW - 1) {
        *(ulonglong2*)&bc[w][l][0] = make_ulonglong2(h2[0], h2[1]);
        *(ulonglong2*)&bc[w][l][4] = make_ulonglong2(h2[2], h2[3]);
        __threadfence_block();
        if (l == 0) vflag[w] = 1;
    }

    #pragma unroll
    for (int p = 0; p < 4; p++) {
        float2 f = unpk(h2[p]);
        int r0 = row0 + 2 * p;
        unsigned short hh, ll;
        bsplit(f.x, hh, ll);
        *(unsigned short*)&g_H3[(size_t)r0 * KP + j]        = hh;
        *(unsigned short*)&g_H3[(size_t)r0 * KP + 512 + j]  = ll;
        *(unsigned short*)&g_H3[(size_t)r0 * KP + 1024 + j] = hh;
        bsplit(f.y, hh, ll);
        *(unsigned short*)&g_H3[(size_t)(r0 + 1) * KP + j]        = hh;
        *(unsigned short*)&g_H3[(size_t)(r0 + 1) * KP + 512 + j]  = ll;
        *(unsigned short*)&g_H3[(size_t)(r0 + 1) * KP + 1024 + j] = hh;
    }
}

// ---------------------------------------------------------------------------
extern "C" void kernel_launch(void* const* d_in, const int* in_sizes, int n_in,
                              void* d_out, int out_size)
{
    const float* x     = (const float*)d_in[0];
    const float* W_in  = (const float*)d_in[1];
    const float* b_in  = (const float*)d_in[2];
    const float* W_hh  = (const float*)d_in[3];
    const float* b_hh  = (const float*)d_in[4];
    const float* W_out = (const float*)d_in[5];
    const float* b_out = (const float*)d_in[6];
    float* out = (float*)d_out;

    float* hptr = nullptr;
    __nv_bfloat16 *a3 = nullptr, *b3i = nullptr, *b3o = nullptr, *h3 = nullptr;
    cudaGetSymbolAddress((void**)&hptr, g_h);
    cudaGetSymbolAddress((void**)&a3,  g_A3);
    cudaGetSymbolAddress((void**)&b3i, g_B3in);
    cudaGetSymbolAddress((void**)&b3o, g_B3out);
    cudaGetSymbolAddress((void**)&h3,  g_H3);

    convA<<<BATCH * 64 / 256, 256>>>(x, a3);
    convW<<<dim3(8, 8), 256>>>(W_in, b3i);
    convW<<<dim3(8, 8), 256>>>(W_out, b3o);

    mma_gemm<<<dim3(HIDN / 32, BATCH / 64), 128>>>(a3, b3i, b_in, hptr, 1);

    scan_kernel<<<BATCH / NB, 512>>>(W_hh, b_hh);

    mma_gemm<<<dim3(HIDN / 32, BATCH / 64), 128>>>(h3, b3o, b_out, out, 0);
}

// round 15
// speedup vs baseline: 1.2681x; 1.0502x over previous
#include <cuda_runtime.h>
#include <cuda_bf16.h>
#include <cstdint>

#define BATCH 1024
#define HIDN  512
#define KP    1536          // packed K: [hi | lo | hi]
#define NB    8             // batch rows per scan CTA (128 CTAs)
#define CH    32            // scan chunk width
#define NCHW  (HIDN / CH)   // 16 scan chunks
#define NCH2  12            // KP / 128  (GEMM K-chunks of 128)

typedef unsigned long long u64;
typedef unsigned int u32;

__device__ float g_h[BATCH * HIDN];
__device__ __align__(16) __nv_bfloat16 g_A3[BATCH * KP];
__device__ __align__(16) __nv_bfloat16 g_B3in[HIDN * KP];
__device__ __align__(16) __nv_bfloat16 g_B3out[HIDN * KP];
__device__ __align__(16) __nv_bfloat16 g_H3[BATCH * KP];
__device__ __align__(16) u32 g_WB[(HIDN - 1) * HIDN];   // bf16x2 {w, b}

// ---- f32x2 helpers ----------------------------------------------------------
__device__ __forceinline__ u64 pack2(float v) {
    u64 r; asm("mov.b64 %0, {%1, %1};" : "=l"(r) : "f"(v)); return r;
}
__device__ __forceinline__ u64 packxy(float x, float y) {
    u64 r; asm("mov.b64 %0, {%1, %2};" : "=l"(r) : "f"(x), "f"(y)); return r;
}
__device__ __forceinline__ float2 unpk(u64 v) {
    float2 f; asm("mov.b64 {%0, %1}, %2;" : "=f"(f.x), "=f"(f.y) : "l"(v)); return f;
}
__device__ __forceinline__ u64 fma2v(u64 a, u64 b, u64 c) {
    u64 d; asm("fma.rn.f32x2 %0, %1, %2, %3;" : "=l"(d) : "l"(a), "l"(b), "l"(c)); return d;
}
__device__ __forceinline__ u64 max2z(u64 v) {
    u64 m;
    asm("{\n\t.reg .f32 a, b;\n\t"
        "mov.b64 {a, b}, %1;\n\t"
        "max.f32 a, a, 0f00000000;\n\t"
        "max.f32 b, b, 0f00000000;\n\t"
        "mov.b64 %0, {a, b};\n\t}"
        : "=l"(m) : "l"(v));
    return m;
}
__device__ __forceinline__ float2 unpk_wb(u32 v) {
    __nv_bfloat162 t = *reinterpret_cast<__nv_bfloat162*>(&v);
    return __bfloat1622float2(t);
}

// ---- misc helpers -----------------------------------------------------------
__device__ __forceinline__ u32 s2u(const void* p) {
    u32 a;
    asm("{ .reg .u64 t; cvta.to.shared.u64 t, %1; cvt.u32.u64 %0, t; }" : "=r"(a) : "l"(p));
    return a;
}
#define SWZ(x) ((x) ^ (((x) >> 3) & 0x70))

__device__ __forceinline__ void bsplit(float a, unsigned short& h, unsigned short& l) {
    __nv_bfloat16 hb = __float2bfloat16(a);
    __nv_bfloat16 lb = __float2bfloat16(a - __bfloat162float(hb));
    h = *(unsigned short*)&hb;
    l = *(unsigned short*)&lb;
}
__device__ __forceinline__ u32 packwb1(float w, float b) {
    __nv_bfloat16 wh = __float2bfloat16(w), bh = __float2bfloat16(b);
    return (u32)(*(unsigned short*)&wh) | ((u32)(*(unsigned short*)&bh) << 16);
}
__device__ __forceinline__ uint4 pack8(const unsigned short* s) {
    uint4 u;
    u.x = (u32)s[0] | ((u32)s[1] << 16);
    u.y = (u32)s[2] | ((u32)s[3] << 16);
    u.z = (u32)s[4] | ((u32)s[5] << 16);
    u.w = (u32)s[6] | ((u32)s[7] << 16);
    return u;
}

__device__ __forceinline__ void ldm4(u32 addr, u32& r0, u32& r1, u32& r2, u32& r3) {
    asm volatile("ldmatrix.sync.aligned.m8n8.x4.shared.b16 {%0,%1,%2,%3}, [%4];"
                 : "=r"(r0), "=r"(r1), "=r"(r2), "=r"(r3) : "r"(addr));
}
__device__ __forceinline__ void mma16816(float* c, const u32* a, const u32* b) {
    asm volatile("mma.sync.aligned.m16n8k16.row.col.f32.bf16.bf16.f32 "
                 "{%0,%1,%2,%3}, {%4,%5,%6,%7}, {%8,%9}, {%0,%1,%2,%3};"
                 : "+f"(c[0]), "+f"(c[1]), "+f"(c[2]), "+f"(c[3])
                 : "r"(a[0]), "r"(a[1]), "r"(a[2]), "r"(a[3]), "r"(b[0]), "r"(b[1]));
}
__device__ __forceinline__ void cpasync16(u32 dst, const void* src) {
    asm volatile("cp.async.cg.shared.global [%0], [%1], 16;" :: "r"(dst), "l"(src));
}

// ---------------------------------------------------------------------------
// convAWB (no smem): blocks [0,256) convA; blocks [256,512) convWB
// ---------------------------------------------------------------------------
__global__ __launch_bounds__(256) void convAWB(
    const float* __restrict__ X, const float* __restrict__ Whh,
    const float* __restrict__ Bhh,
    __nv_bfloat16* __restrict__ A3, u32* __restrict__ WB)
{
    const int b = blockIdx.x, tid = threadIdx.x;
    if (b < 256) {
        int t = b * 256 + tid;
        int m = t >> 6, k8 = (t & 63) << 3;
        float4 v0 = *(const float4*)(X + (size_t)m * 512 + k8);
        float4 v1 = *(const float4*)(X + (size_t)m * 512 + k8 + 4);
        float a[8] = {v0.x, v0.y, v0.z, v0.w, v1.x, v1.y, v1.z, v1.w};
        unsigned short hs[8], ls[8];
        #pragma unroll
        for (int e = 0; e < 8; e++) bsplit(a[e], hs[e], ls[e]);
        uint4 hp = pack8(hs), lp = pack8(ls);
        __nv_bfloat16* base = A3 + (size_t)m * KP + k8;
        *(uint4*)(base)        = hp;
        *(uint4*)(base + 512)  = lp;
        *(uint4*)(base + 1024) = hp;
    } else {
        int i4 = ((b - 256) * 256 + tid) * 4;
        if (i4 < (HIDN - 1) * HIDN) {
            float4 w  = *(const float4*)(Whh + i4);
            float4 bb = *(const float4*)(Bhh + i4);
            uint4 o;
            o.x = packwb1(w.x, bb.x);
            o.y = packwb1(w.y, bb.y);
            o.z = packwb1(w.z, bb.z);
            o.w = packwb1(w.w, bb.w);
            *(uint4*)(WB + i4) = o;
        }
    }
}

// ---------------------------------------------------------------------------
// convW: W [512(k),512(n)] fp32 -> B3 [n][1536] bf16 = [Wh | Wh | Wl] (K-major)
// ---------------------------------------------------------------------------
__global__ __launch_bounds__(256) void convW(
    const float* __restrict__ W, __nv_bfloat16* __restrict__ B3)
{
    __shared__ float tile[64][65];
    const int kb = blockIdx.y * 64, nb = blockIdx.x * 64, tid = threadIdx.x;
    #pragma unroll
    for (int it = 0; it < 16; it++) {
        int idx = tid + it * 256, r = idx >> 6, cn = idx & 63;
        tile[r][cn] = W[(size_t)(kb + r) * 512 + nb + cn];
    }
    __syncthreads();
    const int nl = tid >> 2, kq = (tid & 3) << 4;
    const int row = nb + nl;
    #pragma unroll
    for (int g = 0; g < 2; g++) {
        unsigned short hs[8], ls[8];
        #pragma unroll
        for (int e = 0; e < 8; e++)
            bsplit(tile[kq + g * 8 + e][nl], hs[e], ls[e]);
        uint4 hp = pack8(hs), lp = pack8(ls);
        __nv_bfloat16* base = B3 + (size_t)row * KP + kb + kq + g * 8;
        *(uint4*)(base)        = hp;
        *(uint4*)(base + 512)  = hp;
        *(uint4*)(base + 1024) = lp;
    }
}

// ---------------------------------------------------------------------------
// Warp-MMA bf16 GEMM (R14, 12.1us): CTA 64x32, 128 threads = 2x2 warps,
// K-chunks of 128 as two 64-wide sub-tiles, 3-stage cp.async, 12 barriers.
// ---------------------------------------------------------------------------
__global__ __launch_bounds__(128) void mma_gemm(
    const __nv_bfloat16* __restrict__ A3, const __nv_bfloat16* __restrict__ B3,
    const float* __restrict__ bias, float* __restrict__ C, int act)
{
    __shared__ __align__(128) char As[3 * 16384];
    __shared__ __align__(128) char Bs[3 * 8192];

    const int tid = threadIdx.x, wid = tid >> 5, lane = tid & 31;
    const int wm = wid >> 1, wn = wid & 1;
    const int mbase = blockIdx.y * 64, nbase = blockIdx.x * 32;
    const u32 sA = s2u(As), sB = s2u(Bs);

    const int idx = lane >> 3, lrow = lane & 7;
    u32 off_a[2][4], off_b[4];
    #pragma unroll
    for (int mt = 0; mt < 2; mt++)
        #pragma unroll
        for (int ks = 0; ks < 4; ks++) {
            int m_off = wm * 32 + mt * 16 + (idx & 1) * 8 + lrow;
            int kb    = ks * 32 + (idx >> 1) * 16;
            off_a[mt][ks] = SWZ(m_off * 128 + kb);
        }
    #pragma unroll
    for (int ks = 0; ks < 4; ks++) {
        int n_off = wn * 16 + (idx >> 1) * 8 + lrow;
        int kb    = ks * 32 + (idx & 1) * 16;
        off_b[ks] = SWZ(n_off * 128 + kb);
    }

    float acc[2][2][4];
    #pragma unroll
    for (int mt = 0; mt < 2; mt++)
        #pragma unroll
        for (int nt = 0; nt < 2; nt++)
            #pragma unroll
            for (int e = 0; e < 4; e++) acc[mt][nt][e] = 0.0f;

    const int sr = tid >> 3, sq = tid & 7;

    #pragma unroll
    for (int pc = 0; pc < 2; pc++) {
        #pragma unroll
        for (int s = 0; s < 2; s++) {
            #pragma unroll
            for (int i = 0; i < 4; i++) {
                int r = sr + i * 16;
                cpasync16(sA + pc * 16384 + s * 8192 + SWZ(r * 128 + sq * 16),
                          A3 + (size_t)(mbase + r) * KP + pc * 128 + s * 64 + sq * 8);
            }
            #pragma unroll
            for (int i = 0; i < 2; i++) {
                int r = sr + i * 16;
                cpasync16(sB + pc * 8192 + s * 4096 + SWZ(r * 128 + sq * 16),
                          B3 + (size_t)(nbase + r) * KP + pc * 128 + s * 64 + sq * 8);
            }
        }
        asm volatile("cp.async.commit_group;");
    }

    for (int c = 0; c < NCH2; c++) {
        if (c + 1 < NCH2) asm volatile("cp.async.wait_group 1;");
        else              asm volatile("cp.async.wait_group 0;");
        __syncthreads();

        const int slot = c % 3;
        #pragma unroll
        for (int s = 0; s < 2; s++) {
            const u32 ab = sA + slot * 16384 + s * 8192;
            const u32 bb = sB + slot * 8192  + s * 4096;
            #pragma unroll
            for (int ks = 0; ks < 4; ks++) {
                u32 af[2][4], bf[4];
                ldm4(ab + off_a[0][ks], af[0][0], af[0][1], af[0][2], af[0][3]);
                ldm4(ab + off_a[1][ks], af[1][0], af[1][1], af[1][2], af[1][3]);
                ldm4(bb + off_b[ks], bf[0], bf[1], bf[2], bf[3]);
                mma16816(acc[0][0], af[0], &bf[0]);
                mma16816(acc[0][1], af[0], &bf[2]);
                mma16816(acc[1][0], af[1], &bf[0]);
                mma16816(acc[1][1], af[1], &bf[2]);
            }
        }

        if (c + 2 < NCH2) {
            const int ns = (c + 2) % 3;
            #pragma unroll
            for (int s = 0; s < 2; s++) {
                #pragma unroll
                for (int i = 0; i < 4; i++) {
                    int r = sr + i * 16;
                    cpasync16(sA + ns * 16384 + s * 8192 + SWZ(r * 128 + sq * 16),
                              A3 + (size_t)(mbase + r) * KP + (c + 2) * 128 + s * 64 + sq * 8);
                }
                #pragma unroll
                for (int i = 0; i < 2; i++) {
                    int r = sr + i * 16;
                    cpasync16(sB + ns * 8192 + s * 4096 + SWZ(r * 128 + sq * 16),
                              B3 + (size_t)(nbase + r) * KP + (c + 2) * 128 + s * 64 + sq * 8);
                }
            }
            asm volatile("cp.async.commit_group;");
        }
    }

    #pragma unroll
    for (int mt = 0; mt < 2; mt++) {
        const int row = mbase + wm * 32 + mt * 16 + (lane >> 2);
        #pragma unroll
        for (int nt = 0; nt < 2; nt++) {
            const int col = nbase + wn * 16 + nt * 8 + (lane & 3) * 2;
            float2 bv = *(const float2*)&bias[col];
            float2 o1 = make_float2(acc[mt][nt][0] + bv.x, acc[mt][nt][1] + bv.y);
            float2 o2 = make_float2(acc[mt][nt][2] + bv.x, acc[mt][nt][3] + bv.y);
            if (act) {
                float r;
                r = fmaxf(o1.x, 0.0f); o1.x = r * r;
                r = fmaxf(o1.y, 0.0f); o1.y = r * r;
                r = fmaxf(o2.x, 0.0f); o2.x = r * r;
                r = fmaxf(o2.y, 0.0f); o2.y = r * r;
            }
            *(float2*)&C[(size_t)row * HIDN + col]       = o1;
            *(float2*)&C[(size_t)(row + 8) * HIDN + col] = o2;
        }
    }
}

// ---------------------------------------------------------------------------
// Flag-pipelined sequential scan, NB=8, bf16x2 WB apply path (R11, passed).
// ---------------------------------------------------------------------------
__global__ __launch_bounds__(512) void scan_kernel(
    const float* __restrict__ Whh, const float* __restrict__ Bhh,
    const u32* __restrict__ WB)
{
    const int j    = threadIdx.x;
    const int w    = j >> 5;
    const int l    = j & 31;
    const int row0 = blockIdx.x * NB;

    __shared__ __align__(16) float bc[NCHW][CH][NB];
    __shared__ int flag[NCHW];

    if (j < NCHW) flag[j] = 0;
    __syncthreads();
    volatile int* vflag = flag;

    u64 h2[4];
    #pragma unroll
    for (int p = 0; p < 4; p++)
        h2[p] = packxy(g_h[(size_t)(row0 + 2 * p) * HIDN + j],
                       g_h[(size_t)(row0 + 2 * p + 1) * HIDN + j]);

    for (int c = 0; c < w; c++) {
        const int base = c << 5;
        u32 wb0[16];
        #pragma unroll
        for (int q = 0; q < 16; q++)
            wb0[q] = WB[(size_t)(base + q) * HIDN + j];
        while (vflag[c] == 0) { __nanosleep(64); }
        __threadfence_block();

        u32 wb1[16];
        #pragma unroll
        for (int q = 0; q < 16; q++)
            wb1[q] = WB[(size_t)(base + 16 + q) * HIDN + j];

        #pragma unroll
        for (int q = 0; q < 16; q++) {
            ulonglong2 s01 = *(const ulonglong2*)&bc[c][q][0];
            ulonglong2 s23 = *(const ulonglong2*)&bc[c][q][4];
            u64 s2[4] = {s01.x, s01.y, s23.x, s23.y};
            float2 f = unpk_wb(wb0[q]);
            u64 wd = pack2(f.x), bd = pack2(f.y);
            #pragma unroll
            for (int p = 0; p < 4; p++) {
                u64 m = max2z(fma2v(s2[p], wd, bd));
                h2[p] = fma2v(m, m, h2[p]);
            }
        }
        #pragma unroll
        for (int q = 0; q < 16; q++) {
            ulonglong2 s01 = *(const ulonglong2*)&bc[c][16 + q][0];
            ulonglong2 s23 = *(const ulonglong2*)&bc[c][16 + q][4];
            u64 s2[4] = {s01.x, s01.y, s23.x, s23.y};
            float2 f = unpk_wb(wb1[q]);
            u64 wd = pack2(f.x), bd = pack2(f.y);
            #pragma unroll
            for (int p = 0; p < 4; p++) {
                u64 m = max2z(fma2v(s2[p], wd, bd));
                h2[p] = fma2v(m, m, h2[p]);
            }
        }
    }

    // ---- intra-warp sequential scan of own chunk (fp32 W/B) ----
    const int cbase = w << 5;
    #pragma unroll
    for (int half = 0; half < 2; half++) {
        float wr[16], br[16];
        #pragma unroll
        for (int q = 0; q < 16; q++) {
            int i = cbase + half * 16 + q;
            bool valid = (i < HIDN - 1);
            wr[q] = valid ? Whh[(size_t)i * HIDN + j] : 0.0f;
            br[q] = valid ? Bhh[(size_t)i * HIDN + j] : 0.0f;
        }
        #pragma unroll
        for (int q = 0; q < 16; q++) {
            const int il = half * 16 + q;
            u64 s2[4];
            #pragma unroll
            for (int p = 0; p < 4; p++)
                s2[p] = __shfl_sync(0xffffffffu, h2[p], il);
            if (l > il) {
                u64 wd = pack2(wr[q]), bd = pack2(br[q]);
                #pragma unroll
                for (int p = 0; p < 4; p++) {
                    u64 m = max2z(fma2v(s2[p], wd, bd));
                    h2[p] = fma2v(m, m, h2[p]);
                }
            }
        }
    }

    if (w < NCHW - 1) {
        *(ulonglong2*)&bc[w][l][0] = make_ulonglong2(h2[0], h2[1]);
        *(ulonglong2*)&bc[w][l][4] = make_ulonglong2(h2[2], h2[3]);
        __threadfence_block();
        if (l == 0) vflag[w] = 1;
    }

    #pragma unroll
    for (int p = 0; p < 4; p++) {
        float2 f = unpk(h2[p]);
        int r0 = row0 + 2 * p;
        unsigned short hh, ll;
        bsplit(f.x, hh, ll);
        *(unsigned short*)&g_H3[(size_t)r0 * KP + j]        = hh;
        *(unsigned short*)&g_H3[(size_t)r0 * KP + 512 + j]  = ll;
        *(unsigned short*)&g_H3[(size_t)r0 * KP + 1024 + j] = hh;
        bsplit(f.y, hh, ll);
        *(unsigned short*)&g_H3[(size_t)(r0 + 1) * KP + j]        = hh;
        *(unsigned short*)&g_H3[(size_t)(r0 + 1) * KP + 512 + j]  = ll;
        *(unsigned short*)&g_H3[(size_t)(r0 + 1) * KP + 1024 + j] = hh;
    }
}

// ---------------------------------------------------------------------------
extern "C" void kernel_launch(void* const* d_in, const int* in_sizes, int n_in,
                              void* d_out, int out_size)
{
    const float* x     = (const float*)d_in[0];
    const float* W_in  = (const float*)d_in[1];
    const float* b_in  = (const float*)d_in[2];
    const float* W_hh  = (const float*)d_in[3];
    const float* b_hh  = (const float*)d_in[4];
    const float* W_out = (const float*)d_in[5];
    const float* b_out = (const float*)d_in[6];
    float* out = (float*)d_out;

    float* hptr = nullptr;
    __nv_bfloat16 *a3 = nullptr, *b3i = nullptr, *b3o = nullptr, *h3 = nullptr;
    u32* wb = nullptr;
    cudaGetSymbolAddress((void**)&hptr, g_h);
    cudaGetSymbolAddress((void**)&a3,  g_A3);
    cudaGetSymbolAddress((void**)&b3i, g_B3in);
    cudaGetSymbolAddress((void**)&b3o, g_B3out);
    cudaGetSymbolAddress((void**)&h3,  g_H3);
    cudaGetSymbolAddress((void**)&wb,  g_WB);

    convAWB<<<512, 256>>>(x, W_hh, b_hh, a3, wb);
    convW<<<dim3(8, 8), 256>>>(W_in, b3i);
    convW<<<dim3(8, 8), 256>>>(W_out, b3o);

    mma_gemm<<<dim3(HIDN / 32, BATCH / 64), 128>>>(a3, b3i, b_in, hptr, 1);

    scan_kernel<<<BATCH / NB, 512>>>(W_hh, b_hh, wb);

    mma_gemm<<<dim3(HIDN / 32, BATCH / 64), 128>>>(h3, b3o, b_out, out, 0);
}